// round 7
// baseline (speedup 1.0000x reference)
#include <cuda_runtime.h>
#include <math.h>

// ---------------- problem constants ----------------
#define BDIM   2
#define RDIM   4096
#define NC     48
#define NI     48
#define NRAYS  (BDIM*RDIM)        // 8192
#define NPTS   (NRAYS*NC)         // 393216 per pass
#define HP     256
#define CP     32
#define PLANE_ELEMS (HP*HP)       // 65536
#define PLANESET_FLOATS (BDIM*3*PLANE_ELEMS*CP)  // 12582912

// ---------------- scratch (static device globals; no allocs) ----------------
__device__ float  g_Ttex[PLANESET_FLOATS];   // (b,p,y,x,c) channel-last
__device__ float  g_Tshp[PLANESET_FLOATS];
__device__ float4 g_samp[NRAYS*96];          // rgb + sigma per sample (coarse 0..47, fine 48..95)
__device__ float  g_finez[NRAYS*NI];
__device__ unsigned int g_minmax[2];         // [0]=min bits, [1]=max bits (positive floats)

// ---------------- helpers ----------------
__device__ __forceinline__ float softplusf(float x) {
    return x > 0.f ? x + log1pf(expf(-x)) : log1pf(expf(x));
}

// ---------------- 1) transpose planes to channel-last ----------------
// src layout: (bp, c, yx) with bp in [0,6) per tensor; dst: (bp, yx, c)
__global__ void transpose_kernel(const float* __restrict__ tex,
                                 const float* __restrict__ shp) {
    __shared__ float tile[32][33];
    int t  = blockIdx.y;                    // 0..11 : 6 tex planes then 6 shp planes
    const float* src = (t < 6) ? tex : shp;
    float*       dst = (t < 6) ? g_Ttex : g_Tshp;
    int bp  = (t < 6) ? t : t - 6;
    int yx0 = blockIdx.x * 32;
    int tx = threadIdx.x, ty = threadIdx.y;

    const float* s = src + (size_t)bp * CP * PLANE_ELEMS;
#pragma unroll
    for (int i = 0; i < 4; i++) {
        int c = i * 8 + ty;
        tile[c][tx] = s[(size_t)c * PLANE_ELEMS + yx0 + tx];
    }
    __syncthreads();
    float* d = dst + (size_t)bp * PLANE_ELEMS * CP;
#pragma unroll
    for (int i = 0; i < 4; i++) {
        int row = i * 8 + ty;
        d[(size_t)(yx0 + row) * CP + tx] = tile[tx][row];
    }
}

__global__ void init_kernel() {
    g_minmax[0] = 0x7f800000u;  // +inf
    g_minmax[1] = 0u;           // 0.0f
}

// ---------------- 2) point kernel: plane sampling + MLP ----------------
__device__ __forceinline__ void sample_planeset(const float* __restrict__ T, int b,
                                                float cx, float cy, float cz,
                                                float* __restrict__ f) {
    // plane projections: p0 -> (x,y), p1 -> (x,z), p2 -> (z,x)
    float gus[3] = {cx, cx, cz};
    float gvs[3] = {cy, cz, cx};
#pragma unroll
    for (int p = 0; p < 3; p++) {
        const float* P = T + (size_t)(b * 3 + p) * PLANE_ELEMS * CP;
        float px = (gus[p] + 1.f) * 128.f - 0.5f;
        float py = (gvs[p] + 1.f) * 128.f - 0.5f;
        float fx0 = floorf(px), fy0 = floorf(py);
        int x0 = (int)fx0, y0 = (int)fy0;
        float fx = px - fx0, fy = py - fy0;
#pragma unroll
        for (int dy = 0; dy < 2; dy++) {
#pragma unroll
            for (int dx = 0; dx < 2; dx++) {
                int xi = x0 + dx, yi = y0 + dy;
                float w = (dx ? fx : 1.f - fx) * (dy ? fy : 1.f - fy);
                if (xi >= 0 && xi < HP && yi >= 0 && yi < HP) {
                    const float4* q = (const float4*)(P + ((size_t)yi * HP + xi) * CP);
#pragma unroll
                    for (int i = 0; i < 8; i++) {
                        float4 v = q[i];
                        f[4*i+0] += w * v.x; f[4*i+1] += w * v.y;
                        f[4*i+2] += w * v.z; f[4*i+3] += w * v.w;
                    }
                }
            }
        }
    }
}

__global__ __launch_bounds__(128)
void point_kernel(const float* __restrict__ origins, const float* __restrict__ dirs,
                  const float* __restrict__ W1, const float* __restrict__ b1,
                  const float* __restrict__ W2, const float* __restrict__ b2,
                  const float* __restrict__ noise, int fine) {
    __shared__ float W1s[64*64];
    __shared__ float W2s[64*4];
    __shared__ float b1s[64];
    __shared__ float b2s[4];
    int tid = threadIdx.x;
    for (int i = tid; i < 4096; i += 128) W1s[i] = W1[i];
    for (int i = tid; i < 256;  i += 128) W2s[i] = W2[i];
    if (tid < 64) b1s[tid] = b1[tid];
    if (tid < 4)  b2s[tid] = b2[tid];
    __syncthreads();

    int pid = blockIdx.x * 128 + tid;
    int ray = pid / NC;
    int s   = pid - ray * NC;
    int b   = ray / RDIM;

    float ox = origins[ray*3+0], oy = origins[ray*3+1], oz = origins[ray*3+2];
    float dx = dirs[ray*3+0],    dy = dirs[ray*3+1],    dz = dirs[ray*3+2];
    float inv = rsqrtf(dx*dx + dy*dy + dz*dz);
    dx *= inv; dy *= inv; dz *= inv;

    const float DLT = 0.9f / 47.f;
    float z;
    if (fine) z = g_finez[pid];
    else      z = 0.1f + DLT * ((float)s + noise[pid]);
    float cx = ox + z*dx, cy = oy + z*dy, cz = oz + z*dz;

    float f[64];
#pragma unroll
    for (int i = 0; i < 64; i++) f[i] = 0.f;
    sample_planeset(g_Ttex, b, cx, cy, cz, f);
    sample_planeset(g_Tshp, b, cx, cy, cz, f + 32);
#pragma unroll
    for (int i = 0; i < 64; i++) f[i] *= (1.f / 3.f);

    // MLP: h = softplus(f @ W1 + b1); o = h @ W2 + b2
    float o0 = b2s[0], o1 = b2s[1], o2 = b2s[2], o3 = b2s[3];
#pragma unroll 1
    for (int j = 0; j < 64; j += 4) {
        float a0 = b1s[j], a1 = b1s[j+1], a2 = b1s[j+2], a3 = b1s[j+3];
#pragma unroll
        for (int k = 0; k < 64; k++) {
            float4 w = *(const float4*)&W1s[k*64 + j];
            float fk = f[k];
            a0 += fk * w.x; a1 += fk * w.y; a2 += fk * w.z; a3 += fk * w.w;
        }
        a0 = softplusf(a0); a1 = softplusf(a1); a2 = softplusf(a2); a3 = softplusf(a3);
        float4 u0 = *(const float4*)&W2s[(j+0)*4];
        float4 u1 = *(const float4*)&W2s[(j+1)*4];
        float4 u2 = *(const float4*)&W2s[(j+2)*4];
        float4 u3 = *(const float4*)&W2s[(j+3)*4];
        o0 += a0*u0.x + a1*u1.x + a2*u2.x + a3*u3.x;
        o1 += a0*u0.y + a1*u1.y + a2*u2.y + a3*u3.y;
        o2 += a0*u0.z + a1*u1.z + a2*u2.z + a3*u3.z;
        o3 += a0*u0.w + a1*u1.w + a2*u2.w + a3*u3.w;
    }
    float sg = o0;
    float rr = 1.002f / (1.f + expf(-o1)) - 0.001f;
    float gg = 1.002f / (1.f + expf(-o2)) - 0.001f;
    float bb = 1.002f / (1.f + expf(-o3)) - 0.001f;
    g_samp[ray*96 + s + (fine ? 48 : 0)] = make_float4(rr, gg, bb, sg);
}

// ---------------- 3) importance sampling (1 thread / ray) ----------------
__global__ void imp_kernel(const float* __restrict__ noise,
                           const float* __restrict__ impu) {
    int ray = blockIdx.x * blockDim.x + threadIdx.x;
    if (ray >= NRAYS) return;
    const float DLT = 0.9f / 47.f;

    float z[48];
    for (int i = 0; i < 48; i++)
        z[i] = 0.1f + DLT * ((float)i + noise[ray*48 + i]);

    // coarse ray-march weights
    float w[47];
    float T = 1.f;
    float sp = g_samp[ray*96].w;
    for (int i = 0; i < 47; i++) {
        float sc = g_samp[ray*96 + i + 1].w;
        float dens  = softplusf(0.5f*(sp + sc) - 1.f);
        float alpha = 1.f - expf(-dens * (z[i+1] - z[i]));
        w[i] = alpha * T;
        T *= (1.f - alpha + 1e-10f);
        sp = sc;
    }

    // maxpool + blur + floor; use entries 1..45 (45 pdf weights)
    float bwv[45];
    float S = 0.f;
    for (int j = 1; j <= 45; j++) {
        float mj  = fmaxf(w[j-1], w[j]);             // m[j],  j in 1..45
        float mj1 = fmaxf(w[j],   w[j+1]);           // m[j+1], j+1 in 2..46
        float bw = 0.5f * (mj + mj1) + 0.01f;
        bwv[j-1] = bw; S += bw;
    }
    float invS = 1.f / S;
    float C[46];
    C[0] = 0.f;
    for (int j = 1; j <= 45; j++) C[j] = C[j-1] + bwv[j-1] * invS;

    atomicMin(&g_minmax[0], __float_as_uint(z[0]));
    atomicMax(&g_minmax[1], __float_as_uint(z[47]));

    for (int i = 0; i < 48; i++) {
        float u = impu[ray*48 + i];
        int ind = 0;
        for (int j = 0; j < 46; j++) ind += (C[j] <= u) ? 1 : 0;  // searchsorted right
        int below = ind - 1; if (below < 0) below = 0;
        int above = ind;     if (above > 45) above = 45;
        float c0 = C[below], c1 = C[above];
        float den = c1 - c0; if (den < 1e-5f) den = 1.f;
        float t = (u - c0) / den;
        float bb0 = 0.5f * (z[below] + z[below+1]);   // bins = z_mid
        float bb1 = 0.5f * (z[above] + z[above+1]);
        g_finez[ray*48 + i] = bb0 + t * (bb1 - bb0);
    }
}

// ---------------- 4) final: sort + merge + march (1 thread / ray) ----------------
__global__ void final_kernel(const float* __restrict__ noise,
                             float* __restrict__ out) {
    int ray = blockIdx.x * blockDim.x + threadIdx.x;
    if (ray >= NRAYS) return;
    const float DLT = 0.9f / 47.f;

    float zc[48];
    for (int i = 0; i < 48; i++)
        zc[i] = 0.1f + DLT * ((float)i + noise[ray*48 + i]);

    float fz[48]; int fid[48];
    for (int i = 0; i < 48; i++) { fz[i] = g_finez[ray*48 + i]; fid[i] = i; }
    // stable insertion sort (fine depths)
    for (int i = 1; i < 48; i++) {
        float key = fz[i]; int kid = fid[i];
        int j = i - 1;
        while (j >= 0 && fz[j] > key) { fz[j+1] = fz[j]; fid[j+1] = fid[j]; j--; }
        fz[j+1] = key; fid[j+1] = kid;
    }

    // two-pointer merge (coarse first on ties = stable argsort of concat) + march
    int ic = 0, iff = 0;
    float T = 1.f, accr = 0.f, accg = 0.f, accb = 0.f, wz = 0.f, ws = 0.f;
    float pz = 0.f; float4 ps = make_float4(0.f, 0.f, 0.f, 0.f);
    for (int step = 0; step < 96; step++) {
        float zcur; float4 scur;
        bool takec = (ic < 48) && (iff >= 48 || zc[ic] <= fz[iff]);
        if (takec) { zcur = zc[ic]; scur = g_samp[ray*96 + ic]; ic++; }
        else       { zcur = fz[iff]; scur = g_samp[ray*96 + 48 + fid[iff]]; iff++; }
        if (step > 0) {
            float dlt   = zcur - pz;
            float dens  = softplusf(0.5f*(ps.w + scur.w) - 1.f);
            float alpha = 1.f - expf(-dens * dlt);
            float wgt   = alpha * T;
            accr += wgt * 0.5f * (ps.x + scur.x);
            accg += wgt * 0.5f * (ps.y + scur.y);
            accb += wgt * 0.5f * (ps.z + scur.z);
            wz   += wgt * 0.5f * (pz + zcur);
            ws   += wgt;
            T *= (1.f - alpha + 1e-10f);
        }
        pz = zcur; ps = scur;
    }

    float d = wz / ws;                 // nan/inf -> 0
    if (!isfinite(d)) d = 0.f;
    float gmin = __uint_as_float(g_minmax[0]);
    float gmax = __uint_as_float(g_minmax[1]);
    d = fminf(fmaxf(d, gmin), gmax);

    out[ray*3 + 0] = accr * 2.f - 1.f;
    out[ray*3 + 1] = accg * 2.f - 1.f;
    out[ray*3 + 2] = accb * 2.f - 1.f;
    out[NRAYS*3 + ray] = d;
    out[NRAYS*4 + ray] = ws;
}

// ---------------- launch ----------------
extern "C" void kernel_launch(void* const* d_in, const int* in_sizes, int n_in,
                              void* d_out, int out_size) {
    const float* tex   = (const float*)d_in[0];
    const float* shp   = (const float*)d_in[1];
    const float* orig  = (const float*)d_in[2];
    const float* dirs  = (const float*)d_in[3];
    const float* W1    = (const float*)d_in[4];
    const float* b1    = (const float*)d_in[5];
    const float* W2    = (const float*)d_in[6];
    const float* b2    = (const float*)d_in[7];
    const float* noise = (const float*)d_in[8];
    const float* impu  = (const float*)d_in[9];
    float* out = (float*)d_out;

    transpose_kernel<<<dim3(PLANE_ELEMS/32, 12), dim3(32, 8)>>>(tex, shp);
    init_kernel<<<1, 1>>>();
    point_kernel<<<NPTS/128, 128>>>(orig, dirs, W1, b1, W2, b2, noise, 0);
    imp_kernel<<<NRAYS/128, 128>>>(noise, impu);
    point_kernel<<<NPTS/128, 128>>>(orig, dirs, W1, b1, W2, b2, noise, 1);
    final_kernel<<<NRAYS/128, 128>>>(noise, out);
}

// round 11
// speedup vs baseline: 1.1454x; 1.1454x over previous
#include <cuda_runtime.h>
#include <math.h>

// ---------------- problem constants ----------------
#define BDIM   2
#define RDIM   4096
#define NC     48
#define NI     48
#define NRAYS  (BDIM*RDIM)        // 8192
#define NPTS   (NRAYS*NC)         // 393216 per pass
#define HP     256
#define CP     32
#define PLANE_ELEMS (HP*HP)       // 65536
#define DLT    (0.9f/47.f)

// ---------------- scratch (static device globals; no allocs) ----------------
// combined channel-last planes: (bp, yx, 64ch) ; ch 0..31 = tex, 32..63 = shp
__device__ float4 g_T[6 * PLANE_ELEMS * 16];   // 100.7 MB
__device__ float4 g_samp[NRAYS*96];            // rgb + sigma (coarse 0..47, fine 48..95)
__device__ float  g_finez[NRAYS*NI];
__device__ unsigned int g_minmax[2];           // [0]=min bits, [1]=max bits (positive floats)

// ---------------- f32x2 packed helpers (Blackwell FFMA2) ----------------
typedef unsigned long long u64;
__device__ __forceinline__ u64 ffma2(u64 a, u64 b, u64 c) {
    u64 d; asm("fma.rn.f32x2 %0, %1, %2, %3;" : "=l"(d) : "l"(a), "l"(b), "l"(c)); return d;
}
__device__ __forceinline__ u64 pack2(float lo, float hi) {
    u64 d; asm("mov.b64 %0, {%1, %2};" : "=l"(d) : "f"(lo), "f"(hi)); return d;
}
__device__ __forceinline__ float2 unpack2(u64 v) {
    float2 r; asm("mov.b64 {%0, %1}, %2;" : "=f"(r.x), "=f"(r.y) : "l"(v)); return r;
}

__device__ __forceinline__ float fast_softplus(float x) {
    return fmaxf(x, 0.f) + __logf(1.f + __expf(-fabsf(x)));
}
__device__ __forceinline__ float fast_sigmoid_rgb(float x) {
    return 1.002f / (1.f + __expf(-x)) - 0.001f;
}

// ---------------- 1) transpose + interleave planes to channel-last ----------------
// src: (bp, c, yx) for each of tex/shp ; dst: (bp, yx, 64) with tex in 0..31, shp in 32..63
__global__ void transpose_kernel(const float* __restrict__ tex,
                                 const float* __restrict__ shp) {
    __shared__ float tile[64][33];
    int bp  = blockIdx.y;                  // 0..5
    int yx0 = blockIdx.x * 32;
    int tx = threadIdx.x, ty = threadIdx.y;   // 32 x 8

    const float* st = tex + (size_t)bp * CP * PLANE_ELEMS;
    const float* ss = shp + (size_t)bp * CP * PLANE_ELEMS;
#pragma unroll
    for (int i = 0; i < 4; i++) {
        int c = i * 8 + ty;
        tile[c][tx]      = st[(size_t)c * PLANE_ELEMS + yx0 + tx];
        tile[32 + c][tx] = ss[(size_t)c * PLANE_ELEMS + yx0 + tx];
    }
    __syncthreads();
    float* d = (float*)(g_T + ((size_t)bp * PLANE_ELEMS + yx0) * 16);
#pragma unroll
    for (int i = 0; i < 8; i++) {
        int lin = i * 256 + ty * 32 + tx;     // row = lin/64 (yx), c = lin%64
        d[lin] = tile[lin & 63][lin >> 6];
    }
}

__global__ void init_kernel() {
    g_minmax[0] = 0x7f800000u;  // +inf
    g_minmax[1] = 0u;           // 0.0f
}

// ---------------- 2) point kernel: plane sampling + MLP ----------------
__global__ __launch_bounds__(128)
void point_kernel(const float* __restrict__ origins, const float* __restrict__ dirs,
                  const float* __restrict__ W1, const float* __restrict__ b1,
                  const float* __restrict__ W2, const float* __restrict__ b2,
                  const float* __restrict__ noise, int fine) {
    // W1 transposed: W1ts[j*68 + k] = W1[k*64 + j]  (stride 68: 16B-aligned rows, low-conflict stores)
    __shared__ __align__(16) float W1ts[64 * 68];
    __shared__ __align__(16) float W2ts[4 * 64];   // W2ts[c*64 + j] = W2[j*4 + c]
    __shared__ float b1s[64];
    __shared__ float b2s[4];
    int tid = threadIdx.x;
    for (int i = tid; i < 4096; i += 128) W1ts[(i & 63) * 68 + (i >> 6)] = W1[i];
    for (int i = tid; i < 256;  i += 128) W2ts[(i & 3) * 64 + (i >> 2)] = W2[i];
    if (tid < 64) b1s[tid] = b1[tid];
    if (tid < 4)  b2s[tid] = b2[tid];
    __syncthreads();

    int pid = blockIdx.x * 128 + tid;
    int ray = pid / NC;
    int s   = pid - ray * NC;
    int b   = ray >> 12;               // RDIM = 4096

    float ox = origins[ray*3+0], oy = origins[ray*3+1], oz = origins[ray*3+2];
    float dx = dirs[ray*3+0],    dy = dirs[ray*3+1],    dz = dirs[ray*3+2];
    float inv = rsqrtf(dx*dx + dy*dy + dz*dz);
    dx *= inv; dy *= inv; dz *= inv;

    float z;
    if (fine) z = g_finez[pid];
    else      z = 0.1f + DLT * ((float)s + noise[pid]);
    float cx = ox + z*dx, cy = oy + z*dy, cz = oz + z*dz;

    // ---- gather: 3 planes x 4 bilinear taps, 64 interleaved channels per tap ----
    u64 f2[32];
#pragma unroll
    for (int i = 0; i < 32; i++) f2[i] = 0ull;

    float gus[3] = {cx, cx, cz};
    float gvs[3] = {cy, cz, cx};
#pragma unroll
    for (int p = 0; p < 3; p++) {
        const float4* P = g_T + (size_t)(b * 3 + p) * PLANE_ELEMS * 16;
        float px = (gus[p] + 1.f) * 128.f - 0.5f;
        float py = (gvs[p] + 1.f) * 128.f - 0.5f;
        float fx0 = floorf(px), fy0 = floorf(py);
        int x0 = (int)fx0, y0 = (int)fy0;
        float fx = px - fx0, fy = py - fy0;
#pragma unroll
        for (int dy2 = 0; dy2 < 2; dy2++) {
#pragma unroll
            for (int dx2 = 0; dx2 < 2; dx2++) {
                int xi = x0 + dx2, yi = y0 + dy2;
                float w = (dx2 ? fx : 1.f - fx) * (dy2 ? fy : 1.f - fy) * (1.f / 3.f);
                bool valid = (xi >= 0) & (xi < HP) & (yi >= 0) & (yi < HP);
                w = valid ? w : 0.f;                         // zero weight instead of branch
                int xc = min(max(xi, 0), HP - 1);
                int yc = min(max(yi, 0), HP - 1);
                const ulonglong2* q = (const ulonglong2*)(P + (size_t)(yi = yc * HP + xc, yi) * 16);
                u64 w2 = pack2(w, w);
#pragma unroll
                for (int i = 0; i < 16; i++) {
                    ulonglong2 v = q[i];                     // 4 floats = 2 f32x2 pairs
                    f2[2*i]   = ffma2(w2, v.x, f2[2*i]);
                    f2[2*i+1] = ffma2(w2, v.y, f2[2*i+1]);
                }
            }
        }
    }

    // ---- MLP layer1 (packed over k) with layer2 fused per j-block ----
    u64 oacc[4] = {0ull, 0ull, 0ull, 0ull};
#pragma unroll 1
    for (int jb = 0; jb < 8; jb++) {
        u64 acc[8];
#pragma unroll
        for (int j = 0; j < 8; j++) acc[j] = 0ull;
        const ulonglong2* wr = (const ulonglong2*)(W1ts + (jb * 8) * 68);  // row stride 17 ulonglong2
#pragma unroll
        for (int kk = 0; kk < 16; kk++) {
#pragma unroll
            for (int j = 0; j < 8; j++) {
                ulonglong2 ww = wr[j * 17 + kk];             // W1t[j][4kk..4kk+3], uniform -> broadcast
                acc[j] = ffma2(f2[2*kk],   ww.x, acc[j]);
                acc[j] = ffma2(f2[2*kk+1], ww.y, acc[j]);
            }
        }
        float hh[8];
#pragma unroll
        for (int j = 0; j < 8; j++) {
            float2 pq = unpack2(acc[j]);
            hh[j] = fast_softplus(pq.x + pq.y + b1s[jb * 8 + j]);
        }
#pragma unroll
        for (int t = 0; t < 4; t++) {
            u64 hp = pack2(hh[2*t], hh[2*t+1]);
#pragma unroll
            for (int c = 0; c < 4; c++) {
                u64 wv = ((const u64*)(W2ts + c * 64))[jb * 4 + t];  // pairs over j
                oacc[c] = ffma2(hp, wv, oacc[c]);
            }
        }
    }
    float2 e0 = unpack2(oacc[0]), e1 = unpack2(oacc[1]);
    float2 e2 = unpack2(oacc[2]), e3 = unpack2(oacc[3]);
    float sg = e0.x + e0.y + b2s[0];
    float rr = fast_sigmoid_rgb(e1.x + e1.y + b2s[1]);
    float gg = fast_sigmoid_rgb(e2.x + e2.y + b2s[2]);
    float bb = fast_sigmoid_rgb(e3.x + e3.y + b2s[3]);
    g_samp[ray*96 + s + (fine ? 48 : 0)] = make_float4(rr, gg, bb, sg);
}

// ---------------- 3) importance sampling (1 thread / ray) ----------------
__global__ void imp_kernel(const float* __restrict__ noise,
                           const float* __restrict__ impu) {
    int ray = blockIdx.x * blockDim.x + threadIdx.x;
    if (ray >= NRAYS) return;

    float z[48];
#pragma unroll
    for (int i = 0; i < 48; i++)
        z[i] = 0.1f + DLT * ((float)i + noise[ray*48 + i]);

    // coarse ray-march weights
    float w[47];
    float T = 1.f;
    float sp = g_samp[ray*96].w;
#pragma unroll
    for (int i = 0; i < 47; i++) {
        float sc = g_samp[ray*96 + i + 1].w;
        float dens  = fast_softplus(0.5f*(sp + sc) - 1.f);
        float alpha = 1.f - __expf(-dens * (z[i+1] - z[i]));
        w[i] = alpha * T;
        T *= (1.f - alpha + 1e-10f);
        sp = sc;
    }

    // maxpool + blur + floor; entries 1..45 (45 pdf weights)
    float bwv[45];
    float S = 0.f;
#pragma unroll
    for (int j = 1; j <= 45; j++) {
        float mj  = fmaxf(w[j-1], w[j]);
        float mj1 = fmaxf(w[j],   w[j+1]);
        float bw = 0.5f * (mj + mj1) + 0.01f;
        bwv[j-1] = bw; S += bw;
    }
    float invS = 1.f / S;
    float C[46];
    C[0] = 0.f;
#pragma unroll
    for (int j = 1; j <= 45; j++) C[j] = C[j-1] + bwv[j-1] * invS;

    atomicMin(&g_minmax[0], __float_as_uint(z[0]));
    atomicMax(&g_minmax[1], __float_as_uint(z[47]));

    for (int i = 0; i < 48; i++) {
        float u = impu[ray*48 + i];
        int ind = 0;
#pragma unroll
        for (int j = 0; j < 46; j++) ind += (C[j] <= u) ? 1 : 0;  // searchsorted right
        int below = ind - 1; if (below < 0) below = 0;
        int above = ind;     if (above > 45) above = 45;
        float c0 = C[below], c1 = C[above];
        float den = c1 - c0; if (den < 1e-5f) den = 1.f;
        float t = (u - c0) / den;
        float bb0 = 0.5f * (z[below] + z[below+1]);   // bins = z_mid
        float bb1 = 0.5f * (z[above] + z[above+1]);
        g_finez[ray*48 + i] = bb0 + t * (bb1 - bb0);
    }
}

// ---------------- 4) final: rank-sort + merge + march (1 thread / ray) ----------------
__global__ void final_kernel(const float* __restrict__ noise,
                             float* __restrict__ out) {
    int ray = blockIdx.x * blockDim.x + threadIdx.x;
    if (ray >= NRAYS) return;

    float zc[48];
#pragma unroll
    for (int i = 0; i < 48; i++)
        zc[i] = 0.1f + DLT * ((float)i + noise[ray*48 + i]);

    float fz[48];
#pragma unroll
    for (int i = 0; i < 48; i++) fz[i] = g_finez[ray*48 + i];

    // branchless stable rank sort of fine depths
    float sz[48]; int sid[48];
    for (int i = 0; i < 48; i++) {
        float v = fz[i];
        int r = 0;
#pragma unroll
        for (int j = 0; j < 48; j++)
            r += (fz[j] < v) || (fz[j] == v && j < i);
        sz[r] = v; sid[r] = i;
    }

    // two-pointer merge (coarse first on ties = stable argsort of concat) + march
    int ic = 0, iff = 0;
    float T = 1.f, accr = 0.f, accg = 0.f, accb = 0.f, wz = 0.f, ws = 0.f;
    float pz = 0.f; float4 ps = make_float4(0.f, 0.f, 0.f, 0.f);
    for (int step = 0; step < 96; step++) {
        float zcur; float4 scur;
        bool takec = (ic < 48) && (iff >= 48 || zc[ic] <= sz[iff]);
        if (takec) { zcur = zc[ic]; scur = g_samp[ray*96 + ic]; ic++; }
        else       { zcur = sz[iff]; scur = g_samp[ray*96 + 48 + sid[iff]]; iff++; }
        if (step > 0) {
            float dlt   = zcur - pz;
            float dens  = fast_softplus(0.5f*(ps.w + scur.w) - 1.f);
            float alpha = 1.f - __expf(-dens * dlt);
            float wgt   = alpha * T;
            accr += wgt * 0.5f * (ps.x + scur.x);
            accg += wgt * 0.5f * (ps.y + scur.y);
            accb += wgt * 0.5f * (ps.z + scur.z);
            wz   += wgt * 0.5f * (pz + zcur);
            ws   += wgt;
            T *= (1.f - alpha + 1e-10f);
        }
        pz = zcur; ps = scur;
    }

    float d = wz / ws;                 // nan/inf -> 0
    if (!isfinite(d)) d = 0.f;
    float gmin = __uint_as_float(g_minmax[0]);
    float gmax = __uint_as_float(g_minmax[1]);
    d = fminf(fmaxf(d, gmin), gmax);

    out[ray*3 + 0] = accr * 2.f - 1.f;
    out[ray*3 + 1] = accg * 2.f - 1.f;
    out[ray*3 + 2] = accb * 2.f - 1.f;
    out[NRAYS*3 + ray] = d;
    out[NRAYS*4 + ray] = ws;
}

// ---------------- launch ----------------
extern "C" void kernel_launch(void* const* d_in, const int* in_sizes, int n_in,
                              void* d_out, int out_size) {
    const float* tex   = (const float*)d_in[0];
    const float* shp   = (const float*)d_in[1];
    const float* orig  = (const float*)d_in[2];
    const float* dirs  = (const float*)d_in[3];
    const float* W1    = (const float*)d_in[4];
    const float* b1    = (const float*)d_in[5];
    const float* W2    = (const float*)d_in[6];
    const float* b2    = (const float*)d_in[7];
    const float* noise = (const float*)d_in[8];
    const float* impu  = (const float*)d_in[9];
    float* out = (float*)d_out;

    transpose_kernel<<<dim3(PLANE_ELEMS/32, 6), dim3(32, 8)>>>(tex, shp);
    init_kernel<<<1, 1>>>();
    point_kernel<<<NPTS/128, 128>>>(orig, dirs, W1, b1, W2, b2, noise, 0);
    imp_kernel<<<NRAYS/32, 32>>>(noise, impu);
    point_kernel<<<NPTS/128, 128>>>(orig, dirs, W1, b1, W2, b2, noise, 1);
    final_kernel<<<NRAYS/32, 32>>>(noise, out);
}